// round 17
// baseline (speedup 1.0000x reference)
#include <cuda_runtime.h>

#define NN 8192
#define NBINS 8192                 // bin = fkey >> 19 (sign + exp + 4 mantissa bits)

// ---- K0 (global histogram prepass) ----
#define H_BLOCKS 8                 // per array; each block pre-aggregates 1024 elements

// ---- K1 (rank) ----
#define K1_T 1024
#define K1_SLICES 16               // blocks per array; each ranks NN/K1_SLICES elements
#define K1_EPB (NN / K1_SLICES)    // 512

// ---- tiles / bitmaps ----
#define TILE 256
#define NTILES (NN / TILE)         // 32
#define NWORDS (NN / 32)           // 256 bitmap words per tile

// ---- K3 (count) ----
#define K3_BLOCKS 128              // 64 rows per block
#define K3_T 512                   // 8 lanes per row

// Invariant: g_hist is all-zero at kernel_launch entry (zero-initialized at load;
// count_kernel re-zeroes it at the end of every run).
__device__ unsigned int       g_hist[2][NBINS];
__device__ int                g_r[NN];     // rank of X[p]
__device__ int                g_B[NN];     // argsort(X_hat): B[rank] = index
__device__ int                g_tau[NN];
__device__ unsigned long long g_pb[NTILES * NWORDS]; // (excl. prefix popc << 32) | word
__device__ unsigned int       g_count;
__device__ unsigned int       g_done;

// Monotone uint32 mapping of float (total order == float < for finite values)
__device__ __forceinline__ unsigned int fkey(float f) {
    unsigned int u = __float_as_uint(f);
    return (u & 0x80000000u) ? ~u : (u | 0x80000000u);
}
// Full 45-bit key = (fkey << 13) | idx. bin = fkey >> 19. Within one bin the high
// bits are identical, so ordering == ordering of lo = (fkey << 13) | idx
// (exact stable-argsort index tie-break).

// K0: global histogram with per-block smem pre-aggregation (low global contention).
// grid (H_BLOCKS, 2 arrays), block 1024; each block ingests 1024 elements.
__global__ void hist_kernel(const float* __restrict__ X, const float* __restrict__ Xh) {
    __shared__ unsigned int sh[NBINS];
    const int arr = blockIdx.y;
    const float* __restrict__ src = arr ? Xh : X;
    const int t = threadIdx.x;

    #pragma unroll
    for (int k = 0; k < NBINS / 1024; k++) sh[t + k * 1024] = 0;
    __syncthreads();

    const int e = blockIdx.x * 1024 + t;
    atomicAdd(&sh[fkey(src[e]) >> 19], 1u);
    __syncthreads();

    #pragma unroll
    for (int k = 0; k < NBINS / 1024; k++) {
        const int bin = t + k * 1024;
        const unsigned int c = sh[bin];
        if (c) atomicAdd(&g_hist[arr][bin], c);
    }
}

// K1: exact ranks. Loads the global histogram (no smem hist atomics), scans it,
// scatters lo-keys bin-grouped in smem, compares within bin.
// grid (K1_SLICES, 2 arrays), block K1_T. Dyn smem: cursor | base | binlo | warpsum.
__global__ void rank_kernel(const float* __restrict__ X, const float* __restrict__ Xh) {
    extern __shared__ unsigned int s1[];
    unsigned int* cursor  = s1;                 // [NBINS] excl. prefix -> bin end after scatter
    unsigned int* base    = s1 + NBINS;         // [NBINS] bin start (kept intact)
    unsigned int* binlo   = s1 + 2 * NBINS;     // [NN] low-32 keys grouped by bin
    unsigned int* warpsum = s1 + 3 * NBINS;     // [32]

    const int arr = blockIdx.y;
    const float* __restrict__ src = arr ? Xh : X;
    const int t = threadIdx.x;

    // load global hist (thread t owns bins [8t, 8t+8)) and exclusive-scan it
    unsigned int h[8], tsum = 0;
    #pragma unroll
    for (int k = 0; k < 8; k++) { h[k] = __ldg(&g_hist[arr][t * 8 + k]); tsum += h[k]; }
    unsigned int incl = tsum;
    #pragma unroll
    for (int off = 1; off < 32; off <<= 1) {
        const unsigned int u = __shfl_up_sync(0xffffffffu, incl, off);
        if ((t & 31) >= off) incl += u;
    }
    if ((t & 31) == 31) warpsum[t >> 5] = incl;
    __syncthreads();
    if (t < 32) {
        const unsigned int w = warpsum[t];
        unsigned int wi = w;
        #pragma unroll
        for (int off = 1; off < 32; off <<= 1) {
            const unsigned int u = __shfl_up_sync(0xffffffffu, wi, off);
            if (t >= off) wi += u;
        }
        warpsum[t] = wi - w;   // exclusive warp base
    }
    __syncthreads();
    unsigned int run = warpsum[t >> 5] + (incl - tsum);
    #pragma unroll
    for (int k = 0; k < 8; k++) {
        base[t * 8 + k]   = run;
        cursor[t * 8 + k] = run;
        run += h[k];
    }
    __syncthreads();

    // scatter all lo-keys into bin-grouped order (in-bin order irrelevant)
    #pragma unroll
    for (int k = 0; k < 8; k++) {
        const int e = t + k * K1_T;
        const unsigned int fk = fkey(src[e]);
        const unsigned int lo = (fk << 13) | (unsigned int)e;
        const unsigned int slot = atomicAdd(&cursor[fk >> 19], 1u);
        binlo[slot] = lo;
    }
    __syncthreads();

    // exact rank for this block's slice: 2 lanes per element
    {
        const int e = blockIdx.x * K1_EPB + (t >> 1);
        const int part = t & 1;
        const unsigned int fk = fkey(src[e]);      // L1-hot reload
        const unsigned int mylo = (fk << 13) | (unsigned int)e;
        const unsigned int b = fk >> 19;
        const unsigned int start = base[b];
        const unsigned int end   = cursor[b];      // start + count
        unsigned int cnt = 0;
        for (unsigned int j = start + part; j < end; j += 2)
            cnt += (binlo[j] < mylo) ? 1u : 0u;
        cnt += __shfl_xor_sync(0xffffffffu, cnt, 1);
        if (part == 0) {
            const unsigned int r = start + cnt;
            if (arr) g_B[r] = e;
            else     g_r[e] = (int)r;
        }
    }
}

// K2: build tau and ONE tile's bitmap + exclusive prefix popcounts per block.
// grid NTILES, block TILE.
__global__ void build_kernel() {
    __shared__ unsigned int bm[NWORDS];
    __shared__ unsigned int s_warp[8];
    const int J = blockIdx.x, t = threadIdx.x;

    bm[t] = 0;
    __syncthreads();

    const int i = J * TILE + t;
    const int v = g_B[g_r[i]];
    g_tau[i] = v;
    atomicOr(&bm[v >> 5], 1u << (v & 31));
    __syncthreads();

    // exclusive prefix popcount across the 256 words
    const unsigned int word = bm[t];
    const unsigned int c = __popc(word);
    unsigned int incl = c;
    const int w = t >> 5, l = t & 31;
    #pragma unroll
    for (int off = 1; off < 32; off <<= 1) {
        const unsigned int u = __shfl_up_sync(0xffffffffu, incl, off);
        if (l >= off) incl += u;
    }
    if (l == 31) s_warp[w] = incl;
    __syncthreads();
    if (t < 8) {
        const unsigned int v8 = s_warp[t];
        unsigned int wi = v8;
        #pragma unroll
        for (int off = 1; off < 8; off <<= 1) {
            const unsigned int u = __shfl_up_sync(0xffu, wi, off);
            if (t >= off) wi += u;
        }
        s_warp[t] = wi - v8;   // exclusive warp base
    }
    __syncthreads();
    const unsigned int pref = s_warp[w] + (incl - c);
    g_pb[J * NWORDS + t] = ((unsigned long long)pref << 32) | word;

    if (J == 0 && t == 0) { g_count = 0; g_done = 0; }
}

// K3: inversion count (64 rows/block, 8 lanes/row); finalize in last-done block.
// Also re-zeroes g_hist for the next run (cleanup invariant).
__global__ void __launch_bounds__(K3_T, 2)
count_kernel(float* __restrict__ out) {
    __shared__ int s_tau[TILE];
    __shared__ unsigned int s_sum;
    const int b = blockIdx.x, t = threadIdx.x;
    const int I = b >> 2;                     // this block's position-tile

    // cleanup: zero g_hist (2*NBINS = 16384 words over the first 32 blocks)
    if (b < 32) ((unsigned int*)g_hist)[b * K3_T + t] = 0;

    if (t < TILE) s_tau[t] = g_tau[I * TILE + t];
    if (t == 0) s_sum = 0;
    __syncthreads();

    const int row = t >> 3, part = t & 7;
    const int i  = b * 64 + row;
    const int il = i & (TILE - 1);
    const int v  = s_tau[il];
    unsigned int cnt = 0;

    // within-tile: j in (il, 256), 8-lane strided
    for (int j = il + 1 + part; j < TILE; j += 8)
        cnt += (s_tau[j] < v) ? 1u : 0u;

    // cross-tile: tiles J > I, values < v via packed (pref|word) lookups
    {
        const unsigned int w = (unsigned int)v >> 5;
        const unsigned int mask = (1u << (v & 31)) - 1u;
        for (int J = I + 1 + part; J < NTILES; J += 8) {
            const unsigned long long pb = __ldg(&g_pb[J * NWORDS + w]);
            cnt += (unsigned int)(pb >> 32) + __popc((unsigned int)pb & mask);
        }
    }

    cnt = __reduce_add_sync(0xffffffffu, cnt);
    if ((t & 31) == 0) atomicAdd(&s_sum, cnt);
    __syncthreads();

    if (t == 0) {
        atomicAdd(&g_count, s_sum);
        __threadfence();
        const unsigned int d = atomicAdd(&g_done, 1u);
        if (d == K3_BLOCKS - 1) {
            const unsigned int tot = atomicAdd(&g_count, 0u);
            out[0] = (float)(2.0 * (double)tot / ((double)NN * (double)(NN - 1)));
        }
    }
}

extern "C" void kernel_launch(void* const* d_in, const int* in_sizes, int n_in,
                              void* d_out, int out_size) {
    const float* X  = (const float*)d_in[0];
    const float* Xh = (const float*)d_in[1];
    float* out = (float*)d_out;

    const int smem1 = (3 * NBINS + 32) * (int)sizeof(unsigned int);  // 98,432 B
    cudaFuncSetAttribute(rank_kernel, cudaFuncAttributeMaxDynamicSharedMemorySize, smem1);

    dim3 gh(H_BLOCKS, 2);
    hist_kernel<<<gh, 1024>>>(X, Xh);
    dim3 g1(K1_SLICES, 2);
    rank_kernel<<<g1, K1_T, smem1>>>(X, Xh);
    build_kernel<<<NTILES, TILE>>>();
    count_kernel<<<K3_BLOCKS, K3_T>>>(out);
}